// round 7
// baseline (speedup 1.0000x reference)
#include <cuda_runtime.h>
#include <cuda_fp16.h>
#include <cuda_bf16.h>
#include <cstdint>
#include <cstring>

// Problem dims (fixed by the reference)
#define NROWS   16384
#define INDIM   256
#define OUTDIM  128

// Stage-2 tiling
#define BM 64
#define BK 32
#define KT (NROWS / BK)      // 512
#define NSTG 4               // pipeline stages (A ring and B ring)

// smem (halfs): bufA[NSTG] 64x(40), bufB[NSTG] interleaved 16x264
#define A_BUF_HALFS 2560     // 64 * 40
#define B_BUF_HALFS 4224     // 16 * 264
#define SMEM_AGGR ((NSTG * A_BUF_HALFS + NSTG * B_BUF_HALFS) * 2)   // 54272 B

// Intermediate h in fp16, k-pair interleaved: g_h2[(row>>1)*256 + col*2 + (row&1)]
__device__ __half g_h2[(size_t)NROWS * OUTDIM];

// One dynamic-smem declaration for the whole TU.
extern __shared__ char dyn_smem[];

// ---------------------------------------------------------------------------
__device__ __forceinline__ uint32_t smem_u32(const void* p) {
    uint32_t a;
    asm("{ .reg .u64 t; cvta.to.shared.u64 t, %1; cvt.u32.u64 %0, t; }" : "=r"(a) : "l"(p));
    return a;
}
__device__ __forceinline__ uint32_t f2tf32_rn(float f) {
    uint32_t u;
    asm("cvt.rna.tf32.f32 %0, %1;" : "=r"(u) : "f"(f));
    return u;
}
__device__ __forceinline__ void mma_tf32(float c[4], const uint32_t a[4], const uint32_t b[2]) {
    asm volatile(
        "mma.sync.aligned.m16n8k8.row.col.f32.tf32.tf32.f32 "
        "{%0,%1,%2,%3}, {%4,%5,%6,%7}, {%8,%9}, {%0,%1,%2,%3};"
        : "+f"(c[0]), "+f"(c[1]), "+f"(c[2]), "+f"(c[3])
        : "r"(a[0]), "r"(a[1]), "r"(a[2]), "r"(a[3]), "r"(b[0]), "r"(b[1]));
}
__device__ __forceinline__ void mma_f16(float c[4], const uint32_t a[4], const uint32_t b[2]) {
    asm volatile(
        "mma.sync.aligned.m16n8k16.row.col.f32.f16.f16.f32 "
        "{%0,%1,%2,%3}, {%4,%5,%6,%7}, {%8,%9}, {%0,%1,%2,%3};"
        : "+f"(c[0]), "+f"(c[1]), "+f"(c[2]), "+f"(c[3])
        : "r"(a[0]), "r"(a[1]), "r"(a[2]), "r"(a[3]), "r"(b[0]), "r"(b[1]));
}
__device__ __forceinline__ void cp_async16(uint32_t saddr, const void* g) {
    asm volatile("cp.async.cg.shared.global [%0], [%1], 16;" :: "r"(saddr), "l"(g));
}
__device__ __forceinline__ void cp_commit() { asm volatile("cp.async.commit_group;"); }

// ============================================================================
// Stage 1: h = x @ W^T + b  (tf32, RN both sides) -> g_h2 fp16 interleaved
// ============================================================================
#define A_STRIDE 36
#define LBM 128
__global__ __launch_bounds__(256, 1)
void gemm_lin(const float* __restrict__ x, const float* __restrict__ W,
              const float* __restrict__ bias) {
    float* smem = (float*)dyn_smem;
    float* As0 = smem;
    float* As1 = As0 + LBM * A_STRIDE;
    float* Ws0 = As1 + LBM * A_STRIDE;
    float* Ws1 = Ws0 + OUTDIM * A_STRIDE;

    const int tid  = threadIdx.x;
    const int lane = tid & 31, wid = tid >> 5;
    const int warpM = wid >> 2, warpN = wid & 3;
    const int bm = blockIdx.x;

    uint32_t sA0 = smem_u32(As0), sA1 = smem_u32(As1);
    uint32_t sW0 = smem_u32(Ws0), sW1 = smem_u32(Ws1);

    float c[4][4][4];
#pragma unroll
    for (int i = 0; i < 4; i++)
#pragma unroll
        for (int j = 0; j < 4; j++)
#pragma unroll
            for (int k = 0; k < 4; k++) c[i][j][k] = 0.0f;

    auto load36 = [&](uint32_t sbase, const float* src, int row0, int k0, int ldK) {
#pragma unroll
        for (int t = 0; t < 4; t++) {
            int idx = tid + t * 256;
            int r = idx >> 3, cc = (idx & 7) << 2;
            cp_async16(sbase + (uint32_t)(r * A_STRIDE + cc) * 4u,
                       src + (size_t)(row0 + r) * ldK + k0 + cc);
        }
    };

    load36(sA0, x, bm * LBM, 0, INDIM);
    load36(sW0, W, 0, 0, INDIM);
    cp_commit();

    const int KTL = INDIM / BK; // 8
    for (int kt = 0; kt < KTL; kt++) {
        asm volatile("cp.async.wait_group 0;" ::: "memory");
        __syncthreads();
        if (kt + 1 < KTL) {
            load36(((kt + 1) & 1) ? sA1 : sA0, x, bm * LBM, (kt + 1) * BK, INDIM);
            load36(((kt + 1) & 1) ? sW1 : sW0, W, 0, (kt + 1) * BK, INDIM);
            cp_commit();
        }
        const float* As = (kt & 1) ? As1 : As0;
        const float* Ws = (kt & 1) ? Ws1 : Ws0;

#pragma unroll
        for (int kk = 0; kk < BK; kk += 8) {
            uint32_t af[4][4];
#pragma unroll
            for (int mi = 0; mi < 4; mi++) {
                int r  = warpM * 64 + mi * 16 + (lane >> 2);
                int cc = kk + (lane & 3);
                af[mi][0] = f2tf32_rn(As[r * A_STRIDE + cc]);
                af[mi][1] = f2tf32_rn(As[(r + 8) * A_STRIDE + cc]);
                af[mi][2] = f2tf32_rn(As[r * A_STRIDE + cc + 4]);
                af[mi][3] = f2tf32_rn(As[(r + 8) * A_STRIDE + cc + 4]);
            }
            uint32_t bf[4][2];
#pragma unroll
            for (int ni = 0; ni < 4; ni++) {
                int n = warpN * 32 + ni * 8 + (lane >> 2);
                int k = kk + (lane & 3);
                bf[ni][0] = f2tf32_rn(Ws[n * A_STRIDE + k]);
                bf[ni][1] = f2tf32_rn(Ws[n * A_STRIDE + k + 4]);
            }
#pragma unroll
            for (int mi = 0; mi < 4; mi++)
#pragma unroll
                for (int ni = 0; ni < 4; ni++) mma_tf32(c[mi][ni], af[mi], bf[ni]);
        }
        __syncthreads();
    }

    // Epilogue: bias add, fp16-RN, store into k-pair-interleaved g_h2.
#pragma unroll
    for (int ni = 0; ni < 4; ni++) {
        int cn = warpN * 32 + ni * 8 + ((lane & 3) << 1);
        float2 bb = *(const float2*)(bias + cn);
#pragma unroll
        for (int mi = 0; mi < 4; mi++) {
            int r0 = bm * LBM + warpM * 64 + mi * 16 + (lane >> 2);
            int r1 = r0 + 8;
            size_t b0 = (size_t)(r0 >> 1) * 256 + (r0 & 1);
            size_t b1 = (size_t)(r1 >> 1) * 256 + (r1 & 1);
            g_h2[b0 + (size_t)cn * 2]       = __float2half_rn(c[mi][ni][0] + bb.x);
            g_h2[b0 + (size_t)(cn + 1) * 2] = __float2half_rn(c[mi][ni][1] + bb.y);
            g_h2[b1 + (size_t)cn * 2]       = __float2half_rn(c[mi][ni][2] + bb.x);
            g_h2[b1 + (size_t)(cn + 1) * 2] = __float2half_rn(c[mi][ni][3] + bb.y);
        }
    }
}

// ============================================================================
// Stage 2: out = A_hat @ h, fp16 HMMA m16n8k16.
// BM=64, grid 256, 2 CTAs/SM. 8 warps = 2(M) x 4(N), warp tile 32x32.
// 4-stage cp.async B ring; A converted fp32->fp16 via regs (LDG 2 iters ahead).
// ============================================================================
struct ARegs { float4 v[2]; };   // 8 floats: row tid>>2, k (tid&3)*8 .. +7

__device__ __forceinline__ void ldgA(ARegs& ra, const float* __restrict__ A,
                                     int bm, int kt, int tid) {
    const int row = tid >> 2, kc = (tid & 3) * 8;
    const float* p = A + (size_t)(bm * BM + row) * NROWS + kt * BK + kc;
    ra.v[0] = *(const float4*)p;
    ra.v[1] = *(const float4*)(p + 4);
}

__device__ __forceinline__ void stsA(__half* bufA, const ARegs& ra, int tid) {
    const int row = tid >> 2, kc = (tid & 3) * 8;
    const float* f = (const float*)&ra.v[0];
    __half2 h[4];
#pragma unroll
    for (int j = 0; j < 4; j++) h[j] = __floats2half2_rn(f[2 * j], f[2 * j + 1]);
    uint4 u;
    memcpy(&u, h, 16);
    *(uint4*)&bufA[row * 40 + kc] = u;
}

__device__ __forceinline__ void cpB(uint32_t dstBase, int kt, int tid) {
    const int p0 = kt * 16;   // pair-row base
#pragma unroll
    for (int t = 0; t < 2; t++) {
        int c = tid + t * 256;
        int kp = c >> 5, j = c & 31;
        cp_async16(dstBase + (uint32_t)(kp * 264 + j * 8) * 2u,
                   g_h2 + (size_t)(p0 + kp) * 256 + j * 8);
    }
}

__device__ __forceinline__ void computeTile(const __half* bufA, const __half* bufB,
                                            float c[2][4][4], int lane,
                                            int warpM, int warpN) {
    uint32_t af[2][2][4], bf[2][4][2];
#pragma unroll
    for (int kk = 0; kk < 2; kk++) {
#pragma unroll
        for (int mi = 0; mi < 2; mi++) {
            int r = warpM * 32 + mi * 16 + (lane >> 2);
            int k = kk * 16 + (lane & 3) * 2;
            af[kk][mi][0] = *(const uint32_t*)&bufA[r * 40 + k];
            af[kk][mi][1] = *(const uint32_t*)&bufA[(r + 8) * 40 + k];
            af[kk][mi][2] = *(const uint32_t*)&bufA[r * 40 + k + 8];
            af[kk][mi][3] = *(const uint32_t*)&bufA[(r + 8) * 40 + k + 8];
        }
#pragma unroll
        for (int ni = 0; ni < 4; ni++) {
            int n  = warpN * 32 + ni * 8 + (lane >> 2);
            int kp = kk * 8 + (lane & 3);
            bf[kk][ni][0] = *(const uint32_t*)&bufB[kp * 264 + n * 2];
            bf[kk][ni][1] = *(const uint32_t*)&bufB[(kp + 4) * 264 + n * 2];
        }
    }
#pragma unroll
    for (int kk = 0; kk < 2; kk++)
#pragma unroll
        for (int mi = 0; mi < 2; mi++)
#pragma unroll
            for (int ni = 0; ni < 4; ni++) mma_f16(c[mi][ni], af[kk][mi], bf[kk][ni]);
}

__global__ __launch_bounds__(256, 2)
void gemm_aggr(const float* __restrict__ A, float* __restrict__ out) {
    __half* sm = (__half*)dyn_smem;
    __half* bufA[NSTG];
    __half* bufB[NSTG];
#pragma unroll
    for (int s = 0; s < NSTG; s++) {
        bufA[s] = sm + s * A_BUF_HALFS;
        bufB[s] = sm + NSTG * A_BUF_HALFS + s * B_BUF_HALFS;
    }

    const int tid  = threadIdx.x;
    const int lane = tid & 31, wid = tid >> 5;
    const int warpM = wid >> 2, warpN = wid & 3;
    const int bm = blockIdx.x;

    float c[2][4][4];
#pragma unroll
    for (int i = 0; i < 2; i++)
#pragma unroll
        for (int j = 0; j < 4; j++)
#pragma unroll
            for (int k = 0; k < 4; k++) c[i][j][k] = 0.0f;

    // Prologue: B tiles 0..2 in flight (one group each); A tiles 0,1 stored,
    // A tiles 2,3 staged in registers.
    {
        ARegs t0, t1;
        ldgA(t0, A, bm, 0, tid);
        ldgA(t1, A, bm, 1, tid);
        cpB(smem_u32(bufB[0]), 0, tid); cp_commit();
        cpB(smem_u32(bufB[1]), 1, tid); cp_commit();
        cpB(smem_u32(bufB[2]), 2, tid); cp_commit();
        stsA(bufA[0], t0, tid);
        stsA(bufA[1], t1, tid);
    }
    ARegs ra[2];
    ldgA(ra[0], A, bm, 2, tid);
    ldgA(ra[1], A, bm, 3, tid);

    for (int kt = 0; kt < KT; kt++) {
        // B(kt) complete (issued 3 iterations / 3 groups ago).
        asm volatile("cp.async.wait_group 2;" ::: "memory");
        __syncthreads();

        // Refill the just-freed B stage and keep the A pipeline primed.
        const int nb = kt + 3;          // B tile to fetch
        if (nb < KT) cpB(smem_u32(bufB[nb & (NSTG - 1)]), nb, tid);
        cp_commit();                     // commit unconditionally (group accounting)

        const int na = kt + 2;          // A tile to store (regs loaded 2 iters ago)
        if (na < KT) stsA(bufA[na & (NSTG - 1)], ra[kt & 1], tid);
        const int nl = kt + 4;          // A tile to LDG
        if (nl < KT) ldgA(ra[kt & 1], A, bm, nl, tid);

        computeTile(bufA[kt & (NSTG - 1)], bufB[kt & (NSTG - 1)], c, lane, warpM, warpN);
    }

    // Epilogue
#pragma unroll
    for (int mi = 0; mi < 2; mi++)
#pragma unroll
        for (int ni = 0; ni < 4; ni++) {
            int r  = bm * BM + warpM * 32 + mi * 16 + (lane >> 2);
            int cn = warpN * 32 + ni * 8 + ((lane & 3) << 1);
            *(float2*)&out[(size_t)r * OUTDIM + cn] =
                make_float2(c[mi][ni][0], c[mi][ni][1]);
            *(float2*)&out[(size_t)(r + 8) * OUTDIM + cn] =
                make_float2(c[mi][ni][2], c[mi][ni][3]);
        }
}

static const int SMEM_LIN = (2 * LBM * A_STRIDE + 2 * OUTDIM * A_STRIDE) * 4;  // 73728

extern "C" void kernel_launch(void* const* d_in, const int* in_sizes, int n_in,
                              void* d_out, int out_size) {
    const float* x     = (const float*)d_in[0];
    const float* A_hat = (const float*)d_in[1];
    const float* W     = (const float*)d_in[2];
    const float* b     = (const float*)d_in[3];
    float* out = (float*)d_out;

    cudaFuncSetAttribute(gemm_lin,  cudaFuncAttributeMaxDynamicSharedMemorySize, SMEM_LIN);
    cudaFuncSetAttribute(gemm_aggr, cudaFuncAttributeMaxDynamicSharedMemorySize, SMEM_AGGR);

    gemm_lin<<<NROWS / LBM, 256, SMEM_LIN>>>(x, W, b);
    gemm_aggr<<<NROWS / BM, 256, SMEM_AGGR>>>(A_hat, out);
}

// round 8
// speedup vs baseline: 1.3545x; 1.3545x over previous
#include <cuda_runtime.h>
#include <cuda_fp16.h>
#include <cuda_bf16.h>
#include <cstdint>
#include <cstring>

// Problem dims (fixed by the reference)
#define NROWS   16384
#define INDIM   256
#define OUTDIM  128

// Stage-2 tiling
#define BM 128
#define BK 32
#define KT (NROWS / BK)      // 512
#define NSTG 4               // B pipeline stages

// smem (halfs): bufA[2] 128x40, bufB[NSTG] 16x272 (stride 272 -> conflict-free bf)
#define A_BUF_HALFS 5120     // 128 * 40
#define B_STRIDE_H  272
#define B_BUF_HALFS (16 * B_STRIDE_H)                     // 4352
#define SMEM_AGGR ((2 * A_BUF_HALFS + NSTG * B_BUF_HALFS) * 2)   // 55296 B

// Intermediate h in fp16, k-pair interleaved: g_h2[(row>>1)*256 + col*2 + (row&1)]
__device__ __half g_h2[(size_t)NROWS * OUTDIM];

// One dynamic-smem declaration for the whole TU.
extern __shared__ char dyn_smem[];

// ---------------------------------------------------------------------------
__device__ __forceinline__ uint32_t smem_u32(const void* p) {
    uint32_t a;
    asm("{ .reg .u64 t; cvta.to.shared.u64 t, %1; cvt.u32.u64 %0, t; }" : "=r"(a) : "l"(p));
    return a;
}
__device__ __forceinline__ uint32_t f2tf32_rn(float f) {
    uint32_t u;
    asm("cvt.rna.tf32.f32 %0, %1;" : "=r"(u) : "f"(f));
    return u;
}
__device__ __forceinline__ void mma_tf32(float c[4], const uint32_t a[4], const uint32_t b[2]) {
    asm volatile(
        "mma.sync.aligned.m16n8k8.row.col.f32.tf32.tf32.f32 "
        "{%0,%1,%2,%3}, {%4,%5,%6,%7}, {%8,%9}, {%0,%1,%2,%3};"
        : "+f"(c[0]), "+f"(c[1]), "+f"(c[2]), "+f"(c[3])
        : "r"(a[0]), "r"(a[1]), "r"(a[2]), "r"(a[3]), "r"(b[0]), "r"(b[1]));
}
__device__ __forceinline__ void mma_f16(float c[4], const uint32_t a[4], const uint32_t b[2]) {
    asm volatile(
        "mma.sync.aligned.m16n8k16.row.col.f32.f16.f16.f32 "
        "{%0,%1,%2,%3}, {%4,%5,%6,%7}, {%8,%9}, {%0,%1,%2,%3};"
        : "+f"(c[0]), "+f"(c[1]), "+f"(c[2]), "+f"(c[3])
        : "r"(a[0]), "r"(a[1]), "r"(a[2]), "r"(a[3]), "r"(b[0]), "r"(b[1]));
}
__device__ __forceinline__ void cp_async16(uint32_t saddr, const void* g) {
    asm volatile("cp.async.cg.shared.global [%0], [%1], 16;" :: "r"(saddr), "l"(g));
}
__device__ __forceinline__ void cp_commit() { asm volatile("cp.async.commit_group;"); }

// ============================================================================
// Stage 1: h = x @ W^T + b  (tf32, RN both sides) -> g_h2 fp16 interleaved
// ============================================================================
#define A_STRIDE 36
__global__ __launch_bounds__(256, 1)
void gemm_lin(const float* __restrict__ x, const float* __restrict__ W,
              const float* __restrict__ bias) {
    float* smem = (float*)dyn_smem;
    float* As0 = smem;
    float* As1 = As0 + BM * A_STRIDE;
    float* Ws0 = As1 + BM * A_STRIDE;
    float* Ws1 = Ws0 + OUTDIM * A_STRIDE;

    const int tid  = threadIdx.x;
    const int lane = tid & 31, wid = tid >> 5;
    const int warpM = wid >> 2, warpN = wid & 3;
    const int bm = blockIdx.x;

    uint32_t sA0 = smem_u32(As0), sA1 = smem_u32(As1);
    uint32_t sW0 = smem_u32(Ws0), sW1 = smem_u32(Ws1);

    float c[4][4][4];
#pragma unroll
    for (int i = 0; i < 4; i++)
#pragma unroll
        for (int j = 0; j < 4; j++)
#pragma unroll
            for (int k = 0; k < 4; k++) c[i][j][k] = 0.0f;

    auto load36 = [&](uint32_t sbase, const float* src, int row0, int k0, int ldK) {
#pragma unroll
        for (int t = 0; t < 4; t++) {
            int idx = tid + t * 256;
            int r = idx >> 3, cc = (idx & 7) << 2;
            cp_async16(sbase + (uint32_t)(r * A_STRIDE + cc) * 4u,
                       src + (size_t)(row0 + r) * ldK + k0 + cc);
        }
    };

    load36(sA0, x, bm * BM, 0, INDIM);
    load36(sW0, W, 0, 0, INDIM);
    cp_commit();

    const int KTL = INDIM / BK; // 8
    for (int kt = 0; kt < KTL; kt++) {
        asm volatile("cp.async.wait_group 0;" ::: "memory");
        __syncthreads();
        if (kt + 1 < KTL) {
            load36(((kt + 1) & 1) ? sA1 : sA0, x, bm * BM, (kt + 1) * BK, INDIM);
            load36(((kt + 1) & 1) ? sW1 : sW0, W, 0, (kt + 1) * BK, INDIM);
            cp_commit();
        }
        const float* As = (kt & 1) ? As1 : As0;
        const float* Ws = (kt & 1) ? Ws1 : Ws0;

#pragma unroll
        for (int kk = 0; kk < BK; kk += 8) {
            uint32_t af[4][4];
#pragma unroll
            for (int mi = 0; mi < 4; mi++) {
                int r  = warpM * 64 + mi * 16 + (lane >> 2);
                int cc = kk + (lane & 3);
                af[mi][0] = f2tf32_rn(As[r * A_STRIDE + cc]);
                af[mi][1] = f2tf32_rn(As[(r + 8) * A_STRIDE + cc]);
                af[mi][2] = f2tf32_rn(As[r * A_STRIDE + cc + 4]);
                af[mi][3] = f2tf32_rn(As[(r + 8) * A_STRIDE + cc + 4]);
            }
            uint32_t bf[4][2];
#pragma unroll
            for (int ni = 0; ni < 4; ni++) {
                int n = warpN * 32 + ni * 8 + (lane >> 2);
                int k = kk + (lane & 3);
                bf[ni][0] = f2tf32_rn(Ws[n * A_STRIDE + k]);
                bf[ni][1] = f2tf32_rn(Ws[n * A_STRIDE + k + 4]);
            }
#pragma unroll
            for (int mi = 0; mi < 4; mi++)
#pragma unroll
                for (int ni = 0; ni < 4; ni++) mma_tf32(c[mi][ni], af[mi], bf[ni]);
        }
        __syncthreads();
    }

    // Epilogue: bias add, fp16-RN, store into k-pair-interleaved g_h2.
#pragma unroll
    for (int ni = 0; ni < 4; ni++) {
        int cn = warpN * 32 + ni * 8 + ((lane & 3) << 1);
        float2 bb = *(const float2*)(bias + cn);
#pragma unroll
        for (int mi = 0; mi < 4; mi++) {
            int r0 = bm * BM + warpM * 64 + mi * 16 + (lane >> 2);
            int r1 = r0 + 8;
            size_t b0 = (size_t)(r0 >> 1) * 256 + (r0 & 1);
            size_t b1 = (size_t)(r1 >> 1) * 256 + (r1 & 1);
            g_h2[b0 + (size_t)cn * 2]       = __float2half_rn(c[mi][ni][0] + bb.x);
            g_h2[b0 + (size_t)(cn + 1) * 2] = __float2half_rn(c[mi][ni][1] + bb.y);
            g_h2[b1 + (size_t)cn * 2]       = __float2half_rn(c[mi][ni][2] + bb.x);
            g_h2[b1 + (size_t)(cn + 1) * 2] = __float2half_rn(c[mi][ni][3] + bb.y);
        }
    }
}

// ============================================================================
// Stage 2: out = A_hat @ h, fp16 HMMA m16n8k16.
// BM=128, 8 warps = 2(M) x 4(N), warp tile 64x32.
// B: 4-stage cp.async ring, prefetch distance 3, wait_group 2 (never waits
// on its own iteration's prefetch). A: fp32->fp16 reg-staged, LDG 2 ahead.
// ============================================================================
struct ARegs { float4 v[4]; };   // 16 floats: rows (tid>>2), (tid>>2)+64; 8 k each

__device__ __forceinline__ void ldgA(ARegs& ra, const float* __restrict__ A,
                                     int bm, int kt, int tid) {
    const int row = tid >> 2, kc = (tid & 3) * 8;
    const float* p = A + (size_t)(bm * BM + row) * NROWS + kt * BK + kc;
    ra.v[0] = *(const float4*)p;
    ra.v[1] = *(const float4*)(p + 4);
    const float* q = p + (size_t)64 * NROWS;
    ra.v[2] = *(const float4*)q;
    ra.v[3] = *(const float4*)(q + 4);
}

__device__ __forceinline__ void stsA(__half* bufA, const ARegs& ra, int tid) {
    const int row = tid >> 2, kc = (tid & 3) * 8;
#pragma unroll
    for (int s = 0; s < 2; s++) {
        const float* f = (const float*)&ra.v[s * 2];
        __half2 h[4];
#pragma unroll
        for (int j = 0; j < 4; j++) h[j] = __floats2half2_rn(f[2 * j], f[2 * j + 1]);
        uint4 u;
        memcpy(&u, h, 16);
        *(uint4*)&bufA[(row + s * 64) * 40 + kc] = u;
    }
}

__device__ __forceinline__ void cpB(uint32_t dstBase, int kt, int tid) {
    const int p0 = kt * 16;   // pair-row base
#pragma unroll
    for (int t = 0; t < 2; t++) {
        int c = tid + t * 256;
        int kp = c >> 5, j = c & 31;
        cp_async16(dstBase + (uint32_t)(kp * B_STRIDE_H + j * 8) * 2u,
                   g_h2 + (size_t)(p0 + kp) * 256 + j * 8);
    }
}

__device__ __forceinline__ void computeTile(const __half* bufA, const __half* bufB,
                                            float c[4][4][4], int lane,
                                            int warpM, int warpN) {
    uint32_t af[2][4][4], bf[2][4][2];
#pragma unroll
    for (int kk = 0; kk < 2; kk++) {
#pragma unroll
        for (int mi = 0; mi < 4; mi++) {
            int r = warpM * 64 + mi * 16 + (lane >> 2);
            int k = kk * 16 + (lane & 3) * 2;
            af[kk][mi][0] = *(const uint32_t*)&bufA[r * 40 + k];
            af[kk][mi][1] = *(const uint32_t*)&bufA[(r + 8) * 40 + k];
            af[kk][mi][2] = *(const uint32_t*)&bufA[r * 40 + k + 8];
            af[kk][mi][3] = *(const uint32_t*)&bufA[(r + 8) * 40 + k + 8];
        }
#pragma unroll
        for (int ni = 0; ni < 4; ni++) {
            int n  = warpN * 32 + ni * 8 + (lane >> 2);
            int kp = kk * 8 + (lane & 3);
            bf[kk][ni][0] = *(const uint32_t*)&bufB[kp * B_STRIDE_H + n * 2];
            bf[kk][ni][1] = *(const uint32_t*)&bufB[(kp + 4) * B_STRIDE_H + n * 2];
        }
    }
#pragma unroll
    for (int kk = 0; kk < 2; kk++)
#pragma unroll
        for (int mi = 0; mi < 4; mi++)
#pragma unroll
            for (int ni = 0; ni < 4; ni++) mma_f16(c[mi][ni], af[kk][mi], bf[kk][ni]);
}

__global__ __launch_bounds__(256, 1)
void gemm_aggr(const float* __restrict__ A, float* __restrict__ out) {
    __half* sm = (__half*)dyn_smem;
    __half* bufA[2] = { sm, sm + A_BUF_HALFS };
    __half* bufB[NSTG];
#pragma unroll
    for (int s = 0; s < NSTG; s++) bufB[s] = sm + 2 * A_BUF_HALFS + s * B_BUF_HALFS;

    const int tid  = threadIdx.x;
    const int lane = tid & 31, wid = tid >> 5;
    const int warpM = wid >> 2, warpN = wid & 3;
    const int bm = blockIdx.x;

    float c[4][4][4];
#pragma unroll
    for (int i = 0; i < 4; i++)
#pragma unroll
        for (int j = 0; j < 4; j++)
#pragma unroll
            for (int k = 0; k < 4; k++) c[i][j][k] = 0.0f;

    // Prologue: B tiles 0..2 in flight (one commit group each);
    // A tile 0 stored to smem; A tile 1 staged in registers.
    ARegs ra;
    {
        ARegs t0;
        ldgA(t0, A, bm, 0, tid);
        cpB(smem_u32(bufB[0]), 0, tid); cp_commit();
        cpB(smem_u32(bufB[1]), 1, tid); cp_commit();
        cpB(smem_u32(bufB[2]), 2, tid); cp_commit();
        stsA(bufA[0], t0, tid);
        ldgA(ra, A, bm, 1, tid);
    }

    for (int kt = 0; kt < KT; kt++) {
        // B(kt) arrived (issued 3 groups ago).
        asm volatile("cp.async.wait_group 2;" ::: "memory");
        __syncthreads();   // orders stsA(kt) [last iter] and frees stage (kt+3)&3

        const int nb = kt + 3;
        if (nb < KT) cpB(smem_u32(bufB[nb & (NSTG - 1)]), nb, tid);
        cp_commit();   // unconditional: keeps group accounting uniform

        if (kt + 1 < KT) stsA(bufA[(kt + 1) & 1], ra, tid);
        if (kt + 2 < KT) ldgA(ra, A, bm, kt + 2, tid);

        computeTile(bufA[kt & 1], bufB[kt & (NSTG - 1)], c, lane, warpM, warpN);
    }

    // Epilogue
#pragma unroll
    for (int mi = 0; mi < 4; mi++)
#pragma unroll
        for (int ni = 0; ni < 4; ni++) {
            int r  = bm * BM + warpM * 64 + mi * 16 + (lane >> 2);
            int cn = warpN * 32 + ni * 8 + ((lane & 3) << 1);
            *(float2*)&out[(size_t)r * OUTDIM + cn] =
                make_float2(c[mi][ni][0], c[mi][ni][1]);
            *(float2*)&out[(size_t)(r + 8) * OUTDIM + cn] =
                make_float2(c[mi][ni][2], c[mi][ni][3]);
        }
}

static const int SMEM_LIN = (2 * BM * A_STRIDE + 2 * OUTDIM * A_STRIDE) * 4;  // 73728

extern "C" void kernel_launch(void* const* d_in, const int* in_sizes, int n_in,
                              void* d_out, int out_size) {
    const float* x     = (const float*)d_in[0];
    const float* A_hat = (const float*)d_in[1];
    const float* W     = (const float*)d_in[2];
    const float* b     = (const float*)d_in[3];
    float* out = (float*)d_out;

    cudaFuncSetAttribute(gemm_lin,  cudaFuncAttributeMaxDynamicSharedMemorySize, SMEM_LIN);
    cudaFuncSetAttribute(gemm_aggr, cudaFuncAttributeMaxDynamicSharedMemorySize, SMEM_AGGR);

    gemm_lin<<<NROWS / BM, 256, SMEM_LIN>>>(x, W, b);
    gemm_aggr<<<NROWS / BM, 256, SMEM_AGGR>>>(A_hat, out);
}

// round 9
// speedup vs baseline: 1.6783x; 1.2391x over previous
#include <cuda_runtime.h>
#include <cuda_fp16.h>
#include <cuda_bf16.h>
#include <cstdint>
#include <cstring>

// Problem dims (fixed by the reference)
#define NROWS   16384
#define INDIM   256
#define OUTDIM  128

// Stage-2 tiling
#define BM 128
#define BK 64
#define KT (NROWS / BK)      // 256

// smem (halfs):
//  bufA[2]: two 32-k blocks, each 128 rows x stride 40  -> 10240 halfs/buf
//  bufB[2]: 32 pair-rows x stride 272                   -> 8704 halfs/buf
#define A_BLK_HALFS 5120
#define A_BUF_HALFS (2 * A_BLK_HALFS)    // 10240
#define B_STRIDE_H  272
#define B_BUF_HALFS (32 * B_STRIDE_H)    // 8704
#define SMEM_AGGR ((2 * A_BUF_HALFS + 2 * B_BUF_HALFS) * 2)   // 75776 B

// Intermediate h in fp16, k-pair interleaved: g_h2[(row>>1)*256 + col*2 + (row&1)]
__device__ __half g_h2[(size_t)NROWS * OUTDIM];

// One dynamic-smem declaration for the whole TU.
extern __shared__ char dyn_smem[];

// ---------------------------------------------------------------------------
__device__ __forceinline__ uint32_t smem_u32(const void* p) {
    uint32_t a;
    asm("{ .reg .u64 t; cvta.to.shared.u64 t, %1; cvt.u32.u64 %0, t; }" : "=r"(a) : "l"(p));
    return a;
}
__device__ __forceinline__ uint32_t f2tf32_rn(float f) {
    uint32_t u;
    asm("cvt.rna.tf32.f32 %0, %1;" : "=r"(u) : "f"(f));
    return u;
}
__device__ __forceinline__ void mma_tf32(float c[4], const uint32_t a[4], const uint32_t b[2]) {
    asm volatile(
        "mma.sync.aligned.m16n8k8.row.col.f32.tf32.tf32.f32 "
        "{%0,%1,%2,%3}, {%4,%5,%6,%7}, {%8,%9}, {%0,%1,%2,%3};"
        : "+f"(c[0]), "+f"(c[1]), "+f"(c[2]), "+f"(c[3])
        : "r"(a[0]), "r"(a[1]), "r"(a[2]), "r"(a[3]), "r"(b[0]), "r"(b[1]));
}
__device__ __forceinline__ void mma_f16(float c[4], const uint32_t a[4], const uint32_t b[2]) {
    asm volatile(
        "mma.sync.aligned.m16n8k16.row.col.f32.f16.f16.f32 "
        "{%0,%1,%2,%3}, {%4,%5,%6,%7}, {%8,%9}, {%0,%1,%2,%3};"
        : "+f"(c[0]), "+f"(c[1]), "+f"(c[2]), "+f"(c[3])
        : "r"(a[0]), "r"(a[1]), "r"(a[2]), "r"(a[3]), "r"(b[0]), "r"(b[1]));
}
__device__ __forceinline__ void cp_async16(uint32_t saddr, const void* g) {
    asm volatile("cp.async.cg.shared.global [%0], [%1], 16;" :: "r"(saddr), "l"(g));
}
__device__ __forceinline__ void cp_commit() { asm volatile("cp.async.commit_group;"); }

// ============================================================================
// Stage 1: h = x @ W^T + b  (tf32, RN both sides) -> g_h2 fp16 interleaved
// ============================================================================
#define A_STRIDE 36
#define LINBK 32
__global__ __launch_bounds__(256, 1)
void gemm_lin(const float* __restrict__ x, const float* __restrict__ W,
              const float* __restrict__ bias) {
    float* smem = (float*)dyn_smem;
    float* As0 = smem;
    float* As1 = As0 + BM * A_STRIDE;
    float* Ws0 = As1 + BM * A_STRIDE;
    float* Ws1 = Ws0 + OUTDIM * A_STRIDE;

    const int tid  = threadIdx.x;
    const int lane = tid & 31, wid = tid >> 5;
    const int warpM = wid >> 2, warpN = wid & 3;
    const int bm = blockIdx.x;

    uint32_t sA0 = smem_u32(As0), sA1 = smem_u32(As1);
    uint32_t sW0 = smem_u32(Ws0), sW1 = smem_u32(Ws1);

    float c[4][4][4];
#pragma unroll
    for (int i = 0; i < 4; i++)
#pragma unroll
        for (int j = 0; j < 4; j++)
#pragma unroll
            for (int k = 0; k < 4; k++) c[i][j][k] = 0.0f;

    auto load36 = [&](uint32_t sbase, const float* src, int row0, int k0, int ldK) {
#pragma unroll
        for (int t = 0; t < 4; t++) {
            int idx = tid + t * 256;
            int r = idx >> 3, cc = (idx & 7) << 2;
            cp_async16(sbase + (uint32_t)(r * A_STRIDE + cc) * 4u,
                       src + (size_t)(row0 + r) * ldK + k0 + cc);
        }
    };

    load36(sA0, x, bm * BM, 0, INDIM);
    load36(sW0, W, 0, 0, INDIM);
    cp_commit();

    const int KTL = INDIM / LINBK; // 8
    for (int kt = 0; kt < KTL; kt++) {
        asm volatile("cp.async.wait_group 0;" ::: "memory");
        __syncthreads();
        if (kt + 1 < KTL) {
            load36(((kt + 1) & 1) ? sA1 : sA0, x, bm * BM, (kt + 1) * LINBK, INDIM);
            load36(((kt + 1) & 1) ? sW1 : sW0, W, 0, (kt + 1) * LINBK, INDIM);
            cp_commit();
        }
        const float* As = (kt & 1) ? As1 : As0;
        const float* Ws = (kt & 1) ? Ws1 : Ws0;

#pragma unroll
        for (int kk = 0; kk < LINBK; kk += 8) {
            uint32_t af[4][4];
#pragma unroll
            for (int mi = 0; mi < 4; mi++) {
                int r  = warpM * 64 + mi * 16 + (lane >> 2);
                int cc = kk + (lane & 3);
                af[mi][0] = f2tf32_rn(As[r * A_STRIDE + cc]);
                af[mi][1] = f2tf32_rn(As[(r + 8) * A_STRIDE + cc]);
                af[mi][2] = f2tf32_rn(As[r * A_STRIDE + cc + 4]);
                af[mi][3] = f2tf32_rn(As[(r + 8) * A_STRIDE + cc + 4]);
            }
            uint32_t bf[4][2];
#pragma unroll
            for (int ni = 0; ni < 4; ni++) {
                int n = warpN * 32 + ni * 8 + (lane >> 2);
                int k = kk + (lane & 3);
                bf[ni][0] = f2tf32_rn(Ws[n * A_STRIDE + k]);
                bf[ni][1] = f2tf32_rn(Ws[n * A_STRIDE + k + 4]);
            }
#pragma unroll
            for (int mi = 0; mi < 4; mi++)
#pragma unroll
                for (int ni = 0; ni < 4; ni++) mma_tf32(c[mi][ni], af[mi], bf[ni]);
        }
        __syncthreads();
    }

    // Epilogue: bias add, fp16-RN, store into k-pair-interleaved g_h2.
#pragma unroll
    for (int ni = 0; ni < 4; ni++) {
        int cn = warpN * 32 + ni * 8 + ((lane & 3) << 1);
        float2 bb = *(const float2*)(bias + cn);
#pragma unroll
        for (int mi = 0; mi < 4; mi++) {
            int r0 = bm * BM + warpM * 64 + mi * 16 + (lane >> 2);
            int r1 = r0 + 8;
            size_t b0 = (size_t)(r0 >> 1) * 256 + (r0 & 1);
            size_t b1 = (size_t)(r1 >> 1) * 256 + (r1 & 1);
            g_h2[b0 + (size_t)cn * 2]       = __float2half_rn(c[mi][ni][0] + bb.x);
            g_h2[b0 + (size_t)(cn + 1) * 2] = __float2half_rn(c[mi][ni][1] + bb.y);
            g_h2[b1 + (size_t)cn * 2]       = __float2half_rn(c[mi][ni][2] + bb.x);
            g_h2[b1 + (size_t)(cn + 1) * 2] = __float2half_rn(c[mi][ni][3] + bb.y);
        }
    }
}

// ============================================================================
// Stage 2: out = A_hat @ h, fp16 HMMA m16n8k16, BK=64 (256 iterations).
// R6 loop structure; A tile = 2x stride-40 32-k blocks; B stride-272.
// ============================================================================
struct ARegs { float4 v[8]; };  // 32 floats: rows (tid>>2), (tid>>2)+64; 16 k each

__device__ __forceinline__ void ldgA(ARegs& ra, const float* __restrict__ A,
                                     int bm, int kt, int tid) {
    const int row = tid >> 2, kc = (tid & 3) * 16;
    const float* p = A + (size_t)(bm * BM + row) * NROWS + kt * BK + kc;
#pragma unroll
    for (int j = 0; j < 4; j++) ra.v[j] = *(const float4*)(p + 4 * j);
    const float* q = p + (size_t)64 * NROWS;
#pragma unroll
    for (int j = 0; j < 4; j++) ra.v[4 + j] = *(const float4*)(q + 4 * j);
}

__device__ __forceinline__ void stsA(__half* bufA, const ARegs& ra, int tid) {
    const int s = tid & 3;
    const int blk = s >> 1;            // 32-k sub-block
    const int kcl = (s & 1) * 16;      // k offset within block
#pragma unroll
    for (int half_i = 0; half_i < 2; half_i++) {
        const int row = (tid >> 2) + half_i * 64;
        const float* f = (const float*)&ra.v[half_i * 4];
        __half2 h[8];
#pragma unroll
        for (int j = 0; j < 8; j++) h[j] = __floats2half2_rn(f[2 * j], f[2 * j + 1]);
        uint4 u0, u1;
        memcpy(&u0, &h[0], 16);
        memcpy(&u1, &h[4], 16);
        __half* base = bufA + blk * A_BLK_HALFS + row * 40 + kcl;
        *(uint4*)(base)     = u0;
        *(uint4*)(base + 8) = u1;
    }
}

__device__ __forceinline__ void cpB(uint32_t dstBase, int kt, int tid) {
    const int p0 = kt * 32;   // pair-row base
#pragma unroll
    for (int t = 0; t < 4; t++) {
        int c = tid + t * 256;
        int kp = c >> 5, j = c & 31;
        cp_async16(dstBase + (uint32_t)(kp * B_STRIDE_H + j * 8) * 2u,
                   g_h2 + (size_t)(p0 + kp) * 256 + j * 8);
    }
}

__device__ __forceinline__ void loadFrags(const __half* bufA, const __half* bufB,
                                          int kk, uint32_t af[4][4], uint32_t bf[4][2],
                                          int lane, int warpM, int warpN) {
    const __half* ablk = bufA + (kk >> 1) * A_BLK_HALFS;
    const int kloc = (kk & 1) * 16 + (lane & 3) * 2;
#pragma unroll
    for (int mi = 0; mi < 4; mi++) {
        int r = warpM * 64 + mi * 16 + (lane >> 2);
        af[mi][0] = *(const uint32_t*)&ablk[r * 40 + kloc];
        af[mi][1] = *(const uint32_t*)&ablk[(r + 8) * 40 + kloc];
        af[mi][2] = *(const uint32_t*)&ablk[r * 40 + kloc + 8];
        af[mi][3] = *(const uint32_t*)&ablk[(r + 8) * 40 + kloc + 8];
    }
    const int kp = kk * 8 + (lane & 3);
#pragma unroll
    for (int ni = 0; ni < 4; ni++) {
        int n = warpN * 32 + ni * 8 + (lane >> 2);
        bf[ni][0] = *(const uint32_t*)&bufB[kp * B_STRIDE_H + n * 2];
        bf[ni][1] = *(const uint32_t*)&bufB[(kp + 4) * B_STRIDE_H + n * 2];
    }
}

__device__ __forceinline__ void computeTile(const __half* bufA, const __half* bufB,
                                            float c[4][4][4], int lane,
                                            int warpM, int warpN) {
    uint32_t af[2][4][4], bf[2][4][2];
    loadFrags(bufA, bufB, 0, af[0], bf[0], lane, warpM, warpN);
#pragma unroll
    for (int kk = 0; kk < 4; kk++) {
        if (kk < 3)
            loadFrags(bufA, bufB, kk + 1, af[(kk + 1) & 1], bf[(kk + 1) & 1],
                      lane, warpM, warpN);
#pragma unroll
        for (int mi = 0; mi < 4; mi++)
#pragma unroll
            for (int ni = 0; ni < 4; ni++)
                mma_f16(c[mi][ni], af[kk & 1][mi], bf[kk & 1][ni]);
    }
}

__global__ __launch_bounds__(256, 1)
void gemm_aggr(const float* __restrict__ A, float* __restrict__ out) {
    __half* sm = (__half*)dyn_smem;
    __half* bufA[2] = { sm, sm + A_BUF_HALFS };
    __half* bufB[2] = { sm + 2 * A_BUF_HALFS, sm + 2 * A_BUF_HALFS + B_BUF_HALFS };

    const int tid  = threadIdx.x;
    const int lane = tid & 31, wid = tid >> 5;
    const int warpM = wid >> 2, warpN = wid & 3;
    const int bm = blockIdx.x;

    float c[4][4][4];
#pragma unroll
    for (int i = 0; i < 4; i++)
#pragma unroll
        for (int j = 0; j < 4; j++)
#pragma unroll
            for (int k = 0; k < 4; k++) c[i][j][k] = 0.0f;

    // Prologue (R6 structure): tile0 A+B resident, tile1 A staged in regs.
    ARegs ra;
    {
        ARegs t0;
        ldgA(t0, A, bm, 0, tid);
        cpB(smem_u32(bufB[0]), 0, tid);
        cp_commit();
        stsA(bufA[0], t0, tid);
        ldgA(ra, A, bm, 1, tid);
        asm volatile("cp.async.wait_group 0;" ::: "memory");
        __syncthreads();
    }

    for (int kt = 0; kt < KT; kt++) {
        const int nt1 = (kt + 1 < KT) ? kt + 1 : KT - 1;
        const int nt2 = (kt + 2 < KT) ? kt + 2 : KT - 1;

        // Prefetch tile kt+1 into the other buffers.
        cpB(smem_u32(bufB[(kt + 1) & 1]), nt1, tid);
        cp_commit();
        stsA(bufA[(kt + 1) & 1], ra, tid);
        ldgA(ra, A, bm, nt2, tid);

        // Compute tile kt (covers the cp.async latency of tile kt+1).
        computeTile(bufA[kt & 1], bufB[kt & 1], c, lane, warpM, warpN);

        asm volatile("cp.async.wait_group 0;" ::: "memory");
        __syncthreads();
    }

    // Epilogue
#pragma unroll
    for (int mi = 0; mi < 4; mi++)
#pragma unroll
        for (int ni = 0; ni < 4; ni++) {
            int r  = bm * BM + warpM * 64 + mi * 16 + (lane >> 2);
            int cn = warpN * 32 + ni * 8 + ((lane & 3) << 1);
            *(float2*)&out[(size_t)r * OUTDIM + cn] =
                make_float2(c[mi][ni][0], c[mi][ni][1]);
            *(float2*)&out[(size_t)(r + 8) * OUTDIM + cn] =
                make_float2(c[mi][ni][2], c[mi][ni][3]);
        }
}

static const int SMEM_LIN = (2 * BM * A_STRIDE + 2 * OUTDIM * A_STRIDE) * 4;  // 73728

extern "C" void kernel_launch(void* const* d_in, const int* in_sizes, int n_in,
                              void* d_out, int out_size) {
    const float* x     = (const float*)d_in[0];
    const float* A_hat = (const float*)d_in[1];
    const float* W     = (const float*)d_in[2];
    const float* b     = (const float*)d_in[3];
    float* out = (float*)d_out;

    cudaFuncSetAttribute(gemm_lin,  cudaFuncAttributeMaxDynamicSharedMemorySize, SMEM_LIN);
    cudaFuncSetAttribute(gemm_aggr, cudaFuncAttributeMaxDynamicSharedMemorySize, SMEM_AGGR);

    gemm_lin<<<NROWS / BM, 256, SMEM_LIN>>>(x, W, b);
    gemm_aggr<<<NROWS / BM, 256, SMEM_AGGR>>>(A_hat, out);
}

// round 10
// speedup vs baseline: 1.7397x; 1.0365x over previous
#include <cuda_runtime.h>
#include <cuda_fp16.h>
#include <cuda_bf16.h>
#include <cstdint>
#include <cstring>

// Problem dims (fixed by the reference)
#define NROWS   16384
#define INDIM   256
#define OUTDIM  128

// Stage-2 tiling
#define BM 128
#define BK 32
#define KT (NROWS / BK)      // 512

// smem (halfs): bufA[2] 128x40 fp16, bufB[2] 16x272 fp16
#define A_BUF_HALFS 5120     // 128 * 40
#define B_STRIDE_H  272
#define B_BUF_HALFS (16 * B_STRIDE_H)   // 4352
#define TILE_SMEM ((2 * A_BUF_HALFS + 2 * B_BUF_HALFS) * 2)  // 37888 B
#define RED_SMEM  65536                                       // split-K reduction
#define SMEM_AGGR (RED_SMEM > TILE_SMEM ? RED_SMEM : TILE_SMEM)

// Intermediate h in fp16, k-pair interleaved: g_h2[(row>>1)*256 + col*2 + (row&1)]
__device__ __half g_h2[(size_t)NROWS * OUTDIM];

// One dynamic-smem declaration for the whole TU.
extern __shared__ char dyn_smem[];

// ---------------------------------------------------------------------------
__device__ __forceinline__ uint32_t smem_u32(const void* p) {
    uint32_t a;
    asm("{ .reg .u64 t; cvta.to.shared.u64 t, %1; cvt.u32.u64 %0, t; }" : "=r"(a) : "l"(p));
    return a;
}
__device__ __forceinline__ uint32_t f2tf32_rn(float f) {
    uint32_t u;
    asm("cvt.rna.tf32.f32 %0, %1;" : "=r"(u) : "f"(f));
    return u;
}
__device__ __forceinline__ void mma_tf32(float c[4], const uint32_t a[4], const uint32_t b[2]) {
    asm volatile(
        "mma.sync.aligned.m16n8k8.row.col.f32.tf32.tf32.f32 "
        "{%0,%1,%2,%3}, {%4,%5,%6,%7}, {%8,%9}, {%0,%1,%2,%3};"
        : "+f"(c[0]), "+f"(c[1]), "+f"(c[2]), "+f"(c[3])
        : "r"(a[0]), "r"(a[1]), "r"(a[2]), "r"(a[3]), "r"(b[0]), "r"(b[1]));
}
__device__ __forceinline__ void mma_f16(float c[4], const uint32_t a[4], const uint32_t b[2]) {
    asm volatile(
        "mma.sync.aligned.m16n8k16.row.col.f32.f16.f16.f32 "
        "{%0,%1,%2,%3}, {%4,%5,%6,%7}, {%8,%9}, {%0,%1,%2,%3};"
        : "+f"(c[0]), "+f"(c[1]), "+f"(c[2]), "+f"(c[3])
        : "r"(a[0]), "r"(a[1]), "r"(a[2]), "r"(a[3]), "r"(b[0]), "r"(b[1]));
}
__device__ __forceinline__ void cp_async16(uint32_t saddr, const void* g) {
    asm volatile("cp.async.cg.shared.global [%0], [%1], 16;" :: "r"(saddr), "l"(g));
}
__device__ __forceinline__ void cp_commit() { asm volatile("cp.async.commit_group;"); }

// ============================================================================
// Stage 1: h = x @ W^T + b  (tf32, RN both sides) -> g_h2 fp16 interleaved
// ============================================================================
#define A_STRIDE 36
__global__ __launch_bounds__(256, 1)
void gemm_lin(const float* __restrict__ x, const float* __restrict__ W,
              const float* __restrict__ bias) {
    float* smem = (float*)dyn_smem;
    float* As0 = smem;
    float* As1 = As0 + BM * A_STRIDE;
    float* Ws0 = As1 + BM * A_STRIDE;
    float* Ws1 = Ws0 + OUTDIM * A_STRIDE;

    const int tid  = threadIdx.x;
    const int lane = tid & 31, wid = tid >> 5;
    const int warpM = wid >> 2, warpN = wid & 3;
    const int bm = blockIdx.x;

    uint32_t sA0 = smem_u32(As0), sA1 = smem_u32(As1);
    uint32_t sW0 = smem_u32(Ws0), sW1 = smem_u32(Ws1);

    float c[4][4][4];
#pragma unroll
    for (int i = 0; i < 4; i++)
#pragma unroll
        for (int j = 0; j < 4; j++)
#pragma unroll
            for (int k = 0; k < 4; k++) c[i][j][k] = 0.0f;

    auto load36 = [&](uint32_t sbase, const float* src, int row0, int k0, int ldK) {
#pragma unroll
        for (int t = 0; t < 4; t++) {
            int idx = tid + t * 256;
            int r = idx >> 3, cc = (idx & 7) << 2;
            cp_async16(sbase + (uint32_t)(r * A_STRIDE + cc) * 4u,
                       src + (size_t)(row0 + r) * ldK + k0 + cc);
        }
    };

    load36(sA0, x, bm * BM, 0, INDIM);
    load36(sW0, W, 0, 0, INDIM);
    cp_commit();

    const int KTL = INDIM / BK; // 8
    for (int kt = 0; kt < KTL; kt++) {
        asm volatile("cp.async.wait_group 0;" ::: "memory");
        __syncthreads();
        if (kt + 1 < KTL) {
            load36(((kt + 1) & 1) ? sA1 : sA0, x, bm * BM, (kt + 1) * BK, INDIM);
            load36(((kt + 1) & 1) ? sW1 : sW0, W, 0, (kt + 1) * BK, INDIM);
            cp_commit();
        }
        const float* As = (kt & 1) ? As1 : As0;
        const float* Ws = (kt & 1) ? Ws1 : Ws0;

#pragma unroll
        for (int kk = 0; kk < BK; kk += 8) {
            uint32_t af[4][4];
#pragma unroll
            for (int mi = 0; mi < 4; mi++) {
                int r  = warpM * 64 + mi * 16 + (lane >> 2);
                int cc = kk + (lane & 3);
                af[mi][0] = f2tf32_rn(As[r * A_STRIDE + cc]);
                af[mi][1] = f2tf32_rn(As[(r + 8) * A_STRIDE + cc]);
                af[mi][2] = f2tf32_rn(As[r * A_STRIDE + cc + 4]);
                af[mi][3] = f2tf32_rn(As[(r + 8) * A_STRIDE + cc + 4]);
            }
            uint32_t bf[4][2];
#pragma unroll
            for (int ni = 0; ni < 4; ni++) {
                int n = warpN * 32 + ni * 8 + (lane >> 2);
                int k = kk + (lane & 3);
                bf[ni][0] = f2tf32_rn(Ws[n * A_STRIDE + k]);
                bf[ni][1] = f2tf32_rn(Ws[n * A_STRIDE + k + 4]);
            }
#pragma unroll
            for (int mi = 0; mi < 4; mi++)
#pragma unroll
                for (int ni = 0; ni < 4; ni++) mma_tf32(c[mi][ni], af[mi], bf[ni]);
        }
        __syncthreads();
    }

    // Epilogue: bias add, fp16-RN, store into k-pair-interleaved g_h2.
#pragma unroll
    for (int ni = 0; ni < 4; ni++) {
        int cn = warpN * 32 + ni * 8 + ((lane & 3) << 1);
        float2 bb = *(const float2*)(bias + cn);
#pragma unroll
        for (int mi = 0; mi < 4; mi++) {
            int r0 = bm * BM + warpM * 64 + mi * 16 + (lane >> 2);
            int r1 = r0 + 8;
            size_t b0 = (size_t)(r0 >> 1) * 256 + (r0 & 1);
            size_t b1 = (size_t)(r1 >> 1) * 256 + (r1 & 1);
            g_h2[b0 + (size_t)cn * 2]       = __float2half_rn(c[mi][ni][0] + bb.x);
            g_h2[b0 + (size_t)(cn + 1) * 2] = __float2half_rn(c[mi][ni][1] + bb.y);
            g_h2[b1 + (size_t)cn * 2]       = __float2half_rn(c[mi][ni][2] + bb.x);
            g_h2[b1 + (size_t)(cn + 1) * 2] = __float2half_rn(c[mi][ni][3] + bb.y);
        }
    }
}

// ============================================================================
// Stage 2: out = A_hat @ h, fp16 HMMA m16n8k16.
// 512 threads, 16 warps = 2(M) x 4(N) x 2(K-split). Warp tile 64x32; each
// warp handles ONE m16n8k16 k-step per BK=32 tile. R6 loop skeleton.
// ============================================================================
struct ARegs { float4 v[2]; };   // 8 floats: row tid>>2, k (tid&3)*8 .. +7

__device__ __forceinline__ void ldgA(ARegs& ra, const float* __restrict__ A,
                                     int bm, int kt, int tid) {
    const int row = tid >> 2, kc = (tid & 3) * 8;
    const float* p = A + (size_t)(bm * BM + row) * NROWS + kt * BK + kc;
    ra.v[0] = *(const float4*)p;
    ra.v[1] = *(const float4*)(p + 4);
}

__device__ __forceinline__ void stsA(__half* bufA, const ARegs& ra, int tid) {
    const int row = tid >> 2, kc = (tid & 3) * 8;
    const float* f = (const float*)&ra.v[0];
    __half2 h[4];
#pragma unroll
    for (int j = 0; j < 4; j++) h[j] = __floats2half2_rn(f[2 * j], f[2 * j + 1]);
    uint4 u;
    memcpy(&u, h, 16);
    *(uint4*)&bufA[row * 40 + kc] = u;
}

__device__ __forceinline__ void cpB(uint32_t dstBase, int kt, int tid) {
    const int p0 = kt * 16;          // pair-row base
    const int kp = tid >> 5, j = tid & 31;   // 512 threads -> 512 chunks
    cp_async16(dstBase + (uint32_t)(kp * B_STRIDE_H + j * 8) * 2u,
               g_h2 + (size_t)(p0 + kp) * 256 + j * 8);
}

__device__ __forceinline__ void computeTile(const __half* bufA, const __half* bufB,
                                            float c[4][4][4], int lane,
                                            int warpM, int warpN, int warpK) {
    uint32_t af[4][4], bf[4][2];
    const int kloc = warpK * 16 + (lane & 3) * 2;   // halfs within stride-40 row
#pragma unroll
    for (int mi = 0; mi < 4; mi++) {
        int r = warpM * 64 + mi * 16 + (lane >> 2);
        af[mi][0] = *(const uint32_t*)&bufA[r * 40 + kloc];
        af[mi][1] = *(const uint32_t*)&bufA[(r + 8) * 40 + kloc];
        af[mi][2] = *(const uint32_t*)&bufA[r * 40 + kloc + 8];
        af[mi][3] = *(const uint32_t*)&bufA[(r + 8) * 40 + kloc + 8];
    }
    const int kp = warpK * 8 + (lane & 3);
#pragma unroll
    for (int ni = 0; ni < 4; ni++) {
        int n = warpN * 32 + ni * 8 + (lane >> 2);
        bf[ni][0] = *(const uint32_t*)&bufB[kp * B_STRIDE_H + n * 2];
        bf[ni][1] = *(const uint32_t*)&bufB[(kp + 4) * B_STRIDE_H + n * 2];
    }
#pragma unroll
    for (int mi = 0; mi < 4; mi++)
#pragma unroll
        for (int ni = 0; ni < 4; ni++) mma_f16(c[mi][ni], af[mi], bf[ni]);
}

__global__ __launch_bounds__(512, 1)
void gemm_aggr(const float* __restrict__ A, float* __restrict__ out) {
    __half* sm = (__half*)dyn_smem;
    __half* bufA[2] = { sm, sm + A_BUF_HALFS };
    __half* bufB[2] = { sm + 2 * A_BUF_HALFS, sm + 2 * A_BUF_HALFS + B_BUF_HALFS };

    const int tid  = threadIdx.x;
    const int lane = tid & 31, wid = tid >> 5;     // wid 0..15
    const int warpK = wid >> 3;                    // 0,1
    const int warpM = (wid >> 2) & 1;              // 0,1
    const int warpN = wid & 3;                     // 0..3
    const int bm = blockIdx.x;

    float c[4][4][4];
#pragma unroll
    for (int i = 0; i < 4; i++)
#pragma unroll
        for (int j = 0; j < 4; j++)
#pragma unroll
            for (int k = 0; k < 4; k++) c[i][j][k] = 0.0f;

    // Prologue: tile0 A+B resident, tile1 A staged in regs.
    ARegs ra;
    {
        ARegs t0;
        ldgA(t0, A, bm, 0, tid);
        cpB(smem_u32(bufB[0]), 0, tid);
        cp_commit();
        stsA(bufA[0], t0, tid);
        ldgA(ra, A, bm, 1, tid);
        asm volatile("cp.async.wait_group 0;" ::: "memory");
        __syncthreads();
    }

    for (int kt = 0; kt < KT; kt++) {
        const int nt1 = (kt + 1 < KT) ? kt + 1 : KT - 1;
        const int nt2 = (kt + 2 < KT) ? kt + 2 : KT - 1;

        // Prefetch tile kt+1 into the other buffers.
        cpB(smem_u32(bufB[(kt + 1) & 1]), nt1, tid);
        cp_commit();
        stsA(bufA[(kt + 1) & 1], ra, tid);
        ldgA(ra, A, bm, nt2, tid);

        // Compute tile kt (covers the cp.async latency of tile kt+1).
        computeTile(bufA[kt & 1], bufB[kt & 1], c, lane, warpM, warpN, warpK);

        asm volatile("cp.async.wait_group 0;" ::: "memory");
        __syncthreads();
    }

    // ---- split-K reduction: warpK=1 -> smem, warpK=0 adds & stores ----
    float* red = (float*)dyn_smem;   // 8 warps * 2048 floats = 64 KB
    float4* cf4 = (float4*)&c[0][0][0];   // 16 float4 per thread
    __syncthreads();
    if (warpK == 1) {
        float4* dst = (float4*)(red + (wid - 8) * 2048);
#pragma unroll
        for (int i = 0; i < 16; i++) dst[i * 32 + lane] = cf4[i];
    }
    __syncthreads();
    if (warpK == 0) {
        const float4* src = (const float4*)(red + wid * 2048);
#pragma unroll
        for (int i = 0; i < 16; i++) {
            float4 v = src[i * 32 + lane];
            cf4[i].x += v.x; cf4[i].y += v.y; cf4[i].z += v.z; cf4[i].w += v.w;
        }
#pragma unroll
        for (int mi = 0; mi < 4; mi++)
#pragma unroll
            for (int ni = 0; ni < 4; ni++) {
                int r  = bm * BM + warpM * 64 + mi * 16 + (lane >> 2);
                int cn = warpN * 32 + ni * 8 + ((lane & 3) << 1);
                *(float2*)&out[(size_t)r * OUTDIM + cn] =
                    make_float2(c[mi][ni][0], c[mi][ni][1]);
                *(float2*)&out[(size_t)(r + 8) * OUTDIM + cn] =
                    make_float2(c[mi][ni][2], c[mi][ni][3]);
            }
    }
}

static const int SMEM_LIN = (2 * BM * A_STRIDE + 2 * OUTDIM * A_STRIDE) * 4;  // 73728

extern "C" void kernel_launch(void* const* d_in, const int* in_sizes, int n_in,
                              void* d_out, int out_size) {
    const float* x     = (const float*)d_in[0];
    const float* A_hat = (const float*)d_in[1];
    const float* W     = (const float*)d_in[2];
    const float* b     = (const float*)d_in[3];
    float* out = (float*)d_out;

    cudaFuncSetAttribute(gemm_lin,  cudaFuncAttributeMaxDynamicSharedMemorySize, SMEM_LIN);
    cudaFuncSetAttribute(gemm_aggr, cudaFuncAttributeMaxDynamicSharedMemorySize, SMEM_AGGR);

    gemm_lin<<<NROWS / BM, 256, SMEM_LIN>>>(x, W, b);
    gemm_aggr<<<NROWS / BM, 512, SMEM_AGGR>>>(A_hat, out);
}

// round 11
// speedup vs baseline: 1.7664x; 1.0154x over previous
#include <cuda_runtime.h>
#include <cuda_fp16.h>
#include <cuda_bf16.h>
#include <cstdint>
#include <cstring>

// Problem dims (fixed by the reference)
#define NROWS   16384
#define INDIM   256
#define OUTDIM  128

// Stage-2 tiling
#define BM 128
#define BK 32
#define KT (NROWS / BK)      // 512
#define NB 3                 // B ring stages

// smem (halfs): bufA[2] 128x40 fp16, bufB[NB] 16x272 fp16
#define A_BUF_HALFS 5120     // 128 * 40
#define B_STRIDE_H  272
#define B_BUF_HALFS (16 * B_STRIDE_H)   // 4352
#define TILE_SMEM ((2 * A_BUF_HALFS + NB * B_BUF_HALFS) * 2)  // 46592 B
#define RED_SMEM  65536                                        // split-K reduction
#define SMEM_AGGR (RED_SMEM > TILE_SMEM ? RED_SMEM : TILE_SMEM)

// Intermediate h in fp16, k-pair interleaved: g_h2[(row>>1)*256 + col*2 + (row&1)]
__device__ __half g_h2[(size_t)NROWS * OUTDIM];

// One dynamic-smem declaration for the whole TU.
extern __shared__ char dyn_smem[];

// ---------------------------------------------------------------------------
__device__ __forceinline__ uint32_t smem_u32(const void* p) {
    uint32_t a;
    asm("{ .reg .u64 t; cvta.to.shared.u64 t, %1; cvt.u32.u64 %0, t; }" : "=r"(a) : "l"(p));
    return a;
}
__device__ __forceinline__ uint32_t f2tf32_rn(float f) {
    uint32_t u;
    asm("cvt.rna.tf32.f32 %0, %1;" : "=r"(u) : "f"(f));
    return u;
}
__device__ __forceinline__ void mma_tf32(float c[4], const uint32_t a[4], const uint32_t b[2]) {
    asm volatile(
        "mma.sync.aligned.m16n8k8.row.col.f32.tf32.tf32.f32 "
        "{%0,%1,%2,%3}, {%4,%5,%6,%7}, {%8,%9}, {%0,%1,%2,%3};"
        : "+f"(c[0]), "+f"(c[1]), "+f"(c[2]), "+f"(c[3])
        : "r"(a[0]), "r"(a[1]), "r"(a[2]), "r"(a[3]), "r"(b[0]), "r"(b[1]));
}
__device__ __forceinline__ void mma_f16(float c[4], const uint32_t a[4], const uint32_t b[2]) {
    asm volatile(
        "mma.sync.aligned.m16n8k16.row.col.f32.f16.f16.f32 "
        "{%0,%1,%2,%3}, {%4,%5,%6,%7}, {%8,%9}, {%0,%1,%2,%3};"
        : "+f"(c[0]), "+f"(c[1]), "+f"(c[2]), "+f"(c[3])
        : "r"(a[0]), "r"(a[1]), "r"(a[2]), "r"(a[3]), "r"(b[0]), "r"(b[1]));
}
__device__ __forceinline__ void cp_async16(uint32_t saddr, const void* g) {
    asm volatile("cp.async.cg.shared.global [%0], [%1], 16;" :: "r"(saddr), "l"(g));
}
__device__ __forceinline__ void cp_commit() { asm volatile("cp.async.commit_group;"); }

// ============================================================================
// Stage 1: h = x @ W^T + b  (tf32, RN both sides) -> g_h2 fp16 interleaved
// ============================================================================
#define A_STRIDE 36
__global__ __launch_bounds__(256, 1)
void gemm_lin(const float* __restrict__ x, const float* __restrict__ W,
              const float* __restrict__ bias) {
    float* smem = (float*)dyn_smem;
    float* As0 = smem;
    float* As1 = As0 + BM * A_STRIDE;
    float* Ws0 = As1 + BM * A_STRIDE;
    float* Ws1 = Ws0 + OUTDIM * A_STRIDE;

    const int tid  = threadIdx.x;
    const int lane = tid & 31, wid = tid >> 5;
    const int warpM = wid >> 2, warpN = wid & 3;
    const int bm = blockIdx.x;

    uint32_t sA0 = smem_u32(As0), sA1 = smem_u32(As1);
    uint32_t sW0 = smem_u32(Ws0), sW1 = smem_u32(Ws1);

    float c[4][4][4];
#pragma unroll
    for (int i = 0; i < 4; i++)
#pragma unroll
        for (int j = 0; j < 4; j++)
#pragma unroll
            for (int k = 0; k < 4; k++) c[i][j][k] = 0.0f;

    auto load36 = [&](uint32_t sbase, const float* src, int row0, int k0, int ldK) {
#pragma unroll
        for (int t = 0; t < 4; t++) {
            int idx = tid + t * 256;
            int r = idx >> 3, cc = (idx & 7) << 2;
            cp_async16(sbase + (uint32_t)(r * A_STRIDE + cc) * 4u,
                       src + (size_t)(row0 + r) * ldK + k0 + cc);
        }
    };

    load36(sA0, x, bm * BM, 0, INDIM);
    load36(sW0, W, 0, 0, INDIM);
    cp_commit();

    const int KTL = INDIM / BK; // 8
    for (int kt = 0; kt < KTL; kt++) {
        asm volatile("cp.async.wait_group 0;" ::: "memory");
        __syncthreads();
        if (kt + 1 < KTL) {
            load36(((kt + 1) & 1) ? sA1 : sA0, x, bm * BM, (kt + 1) * BK, INDIM);
            load36(((kt + 1) & 1) ? sW1 : sW0, W, 0, (kt + 1) * BK, INDIM);
            cp_commit();
        }
        const float* As = (kt & 1) ? As1 : As0;
        const float* Ws = (kt & 1) ? Ws1 : Ws0;

#pragma unroll
        for (int kk = 0; kk < BK; kk += 8) {
            uint32_t af[4][4];
#pragma unroll
            for (int mi = 0; mi < 4; mi++) {
                int r  = warpM * 64 + mi * 16 + (lane >> 2);
                int cc = kk + (lane & 3);
                af[mi][0] = f2tf32_rn(As[r * A_STRIDE + cc]);
                af[mi][1] = f2tf32_rn(As[(r + 8) * A_STRIDE + cc]);
                af[mi][2] = f2tf32_rn(As[r * A_STRIDE + cc + 4]);
                af[mi][3] = f2tf32_rn(As[(r + 8) * A_STRIDE + cc + 4]);
            }
            uint32_t bf[4][2];
#pragma unroll
            for (int ni = 0; ni < 4; ni++) {
                int n = warpN * 32 + ni * 8 + (lane >> 2);
                int k = kk + (lane & 3);
                bf[ni][0] = f2tf32_rn(Ws[n * A_STRIDE + k]);
                bf[ni][1] = f2tf32_rn(Ws[n * A_STRIDE + k + 4]);
            }
#pragma unroll
            for (int mi = 0; mi < 4; mi++)
#pragma unroll
                for (int ni = 0; ni < 4; ni++) mma_tf32(c[mi][ni], af[mi], bf[ni]);
        }
        __syncthreads();
    }

    // Epilogue: bias add, fp16-RN, store into k-pair-interleaved g_h2.
#pragma unroll
    for (int ni = 0; ni < 4; ni++) {
        int cn = warpN * 32 + ni * 8 + ((lane & 3) << 1);
        float2 bb = *(const float2*)(bias + cn);
#pragma unroll
        for (int mi = 0; mi < 4; mi++) {
            int r0 = bm * BM + warpM * 64 + mi * 16 + (lane >> 2);
            int r1 = r0 + 8;
            size_t b0 = (size_t)(r0 >> 1) * 256 + (r0 & 1);
            size_t b1 = (size_t)(r1 >> 1) * 256 + (r1 & 1);
            g_h2[b0 + (size_t)cn * 2]       = __float2half_rn(c[mi][ni][0] + bb.x);
            g_h2[b0 + (size_t)(cn + 1) * 2] = __float2half_rn(c[mi][ni][1] + bb.y);
            g_h2[b1 + (size_t)cn * 2]       = __float2half_rn(c[mi][ni][2] + bb.x);
            g_h2[b1 + (size_t)(cn + 1) * 2] = __float2half_rn(c[mi][ni][3] + bb.y);
        }
    }
}

// ============================================================================
// Stage 2: out = A_hat @ h, fp16 HMMA m16n8k16.
// 512 threads, 16 warps = 2(M) x 4(N) x 2(K-split). Warp tile 64x32; each
// warp handles ONE m16n8k16 k-step per BK=32 tile.
// B: 3-stage ring, prefetch distance 2, wait_group 1 -> compute(kt) never
// waits on traffic issued in its own iteration.
// ============================================================================
struct ARegs { float4 v[2]; };   // 8 floats: row tid>>2, k (tid&3)*8 .. +7

__device__ __forceinline__ void ldgA(ARegs& ra, const float* __restrict__ A,
                                     int bm, int kt, int tid) {
    const int row = tid >> 2, kc = (tid & 3) * 8;
    const float* p = A + (size_t)(bm * BM + row) * NROWS + kt * BK + kc;
    ra.v[0] = *(const float4*)p;
    ra.v[1] = *(const float4*)(p + 4);
}

__device__ __forceinline__ void stsA(__half* bufA, const ARegs& ra, int tid) {
    const int row = tid >> 2, kc = (tid & 3) * 8;
    const float* f = (const float*)&ra.v[0];
    __half2 h[4];
#pragma unroll
    for (int j = 0; j < 4; j++) h[j] = __floats2half2_rn(f[2 * j], f[2 * j + 1]);
    uint4 u;
    memcpy(&u, h, 16);
    *(uint4*)&bufA[row * 40 + kc] = u;
}

__device__ __forceinline__ void cpB(uint32_t dstBase, int kt, int tid) {
    const int p0 = kt * 16;          // pair-row base
    const int kp = tid >> 5, j = tid & 31;   // 512 threads -> 512 chunks
    cp_async16(dstBase + (uint32_t)(kp * B_STRIDE_H + j * 8) * 2u,
               g_h2 + (size_t)(p0 + kp) * 256 + j * 8);
}

__device__ __forceinline__ void computeTile(const __half* bufA, const __half* bufB,
                                            float c[4][4][4], int lane,
                                            int warpM, int warpN, int warpK) {
    uint32_t af[4][4], bf[4][2];
    const int kloc = warpK * 16 + (lane & 3) * 2;   // halfs within stride-40 row
#pragma unroll
    for (int mi = 0; mi < 4; mi++) {
        int r = warpM * 64 + mi * 16 + (lane >> 2);
        af[mi][0] = *(const uint32_t*)&bufA[r * 40 + kloc];
        af[mi][1] = *(const uint32_t*)&bufA[(r + 8) * 40 + kloc];
        af[mi][2] = *(const uint32_t*)&bufA[r * 40 + kloc + 8];
        af[mi][3] = *(const uint32_t*)&bufA[(r + 8) * 40 + kloc + 8];
    }
    const int kp = warpK * 8 + (lane & 3);
#pragma unroll
    for (int ni = 0; ni < 4; ni++) {
        int n = warpN * 32 + ni * 8 + (lane >> 2);
        bf[ni][0] = *(const uint32_t*)&bufB[kp * B_STRIDE_H + n * 2];
        bf[ni][1] = *(const uint32_t*)&bufB[(kp + 4) * B_STRIDE_H + n * 2];
    }
#pragma unroll
    for (int mi = 0; mi < 4; mi++)
#pragma unroll
        for (int ni = 0; ni < 4; ni++) mma_f16(c[mi][ni], af[mi], bf[ni]);
}

__global__ __launch_bounds__(512, 1)
void gemm_aggr(const float* __restrict__ A, float* __restrict__ out) {
    __half* sm = (__half*)dyn_smem;
    __half* bufA[2] = { sm, sm + A_BUF_HALFS };
    __half* bufB[NB];
#pragma unroll
    for (int s = 0; s < NB; s++) bufB[s] = sm + 2 * A_BUF_HALFS + s * B_BUF_HALFS;

    const int tid  = threadIdx.x;
    const int lane = tid & 31, wid = tid >> 5;     // wid 0..15
    const int warpK = wid >> 3;                    // 0,1
    const int warpM = (wid >> 2) & 1;              // 0,1
    const int warpN = wid & 3;                     // 0..3
    const int bm = blockIdx.x;

    float c[4][4][4];
#pragma unroll
    for (int i = 0; i < 4; i++)
#pragma unroll
        for (int j = 0; j < 4; j++)
#pragma unroll
            for (int k = 0; k < 4; k++) c[i][j][k] = 0.0f;

    // Prologue: B tiles 0,1 in flight; A tile 0 in smem, tile 1 in regs.
    ARegs ra;
    {
        ARegs t0;
        ldgA(t0, A, bm, 0, tid);
        cpB(smem_u32(bufB[0]), 0, tid); cp_commit();
        cpB(smem_u32(bufB[1]), 1, tid); cp_commit();
        stsA(bufA[0], t0, tid);
        ldgA(ra, A, bm, 1, tid);
        asm volatile("cp.async.wait_group 1;" ::: "memory");   // tile0 done
        __syncthreads();
    }

    int sb = 0;                      // compute B stage = kt % 3
    int wb = 2;                      // write  B stage = (kt+2) % 3
    for (int kt = 0; kt < KT; kt++) {
        const int nb  = (kt + 2 < KT) ? kt + 2 : KT - 1;   // B tile to fetch
        const int nt2 = (kt + 2 < KT) ? kt + 2 : KT - 1;   // A tile to LDG

        cpB(smem_u32(bufB[wb]), nb, tid);
        cp_commit();
        if (kt + 1 < KT) stsA(bufA[(kt + 1) & 1], ra, tid);
        ldgA(ra, A, bm, nt2, tid);

        // Compute tile kt: its B load completed at the previous iteration's wait.
        computeTile(bufA[kt & 1], bufB[sb], c, lane, warpM, warpN, warpK);

        // Drain down to 1 pending group: tile kt+1 complete, tile kt+2 in flight.
        asm volatile("cp.async.wait_group 1;" ::: "memory");
        __syncthreads();

        if (++sb == NB) sb = 0;
        if (++wb == NB) wb = 0;
    }

    // ---- split-K reduction: warpK=1 -> smem, warpK=0 adds & stores ----
    float* red = (float*)dyn_smem;   // 8 warps * 2048 floats = 64 KB
    float4* cf4 = (float4*)&c[0][0][0];   // 16 float4 per thread
    __syncthreads();
    if (warpK == 1) {
        float4* dst = (float4*)(red + (wid - 8) * 2048);
#pragma unroll
        for (int i = 0; i < 16; i++) dst[i * 32 + lane] = cf4[i];
    }
    __syncthreads();
    if (warpK == 0) {
        const float4* src = (const float4*)(red + wid * 2048);
#pragma unroll
        for (int i = 0; i < 16; i++) {
            float4 v = src[i * 32 + lane];
            cf4[i].x += v.x; cf4[i].y += v.y; cf4[i].z += v.z; cf4[i].w += v.w;
        }
#pragma unroll
        for (int mi = 0; mi < 4; mi++)
#pragma unroll
            for (int ni = 0; ni < 4; ni++) {
                int r  = bm * BM + warpM * 64 + mi * 16 + (lane >> 2);
                int cn = warpN * 32 + ni * 8 + ((lane & 3) << 1);
                *(float2*)&out[(size_t)r * OUTDIM + cn] =
                    make_float2(c[mi][ni][0], c[mi][ni][1]);
                *(float2*)&out[(size_t)(r + 8) * OUTDIM + cn] =
                    make_float2(c[mi][ni][2], c[mi][ni][3]);
            }
    }
}

static const int SMEM_LIN = (2 * BM * A_STRIDE + 2 * OUTDIM * A_STRIDE) * 4;  // 73728

extern "C" void kernel_launch(void* const* d_in, const int* in_sizes, int n_in,
                              void* d_out, int out_size) {
    const float* x     = (const float*)d_in[0];
    const float* A_hat = (const float*)d_in[1];
    const float* W     = (const float*)d_in[2];
    const float* b     = (const float*)d_in[3];
    float* out = (float*)d_out;

    cudaFuncSetAttribute(gemm_lin,  cudaFuncAttributeMaxDynamicSharedMemorySize, SMEM_LIN);
    cudaFuncSetAttribute(gemm_aggr, cudaFuncAttributeMaxDynamicSharedMemorySize, SMEM_AGGR);

    gemm_lin<<<NROWS / BM, 256, SMEM_LIN>>>(x, W, b);
    gemm_aggr<<<NROWS / BM, 512, SMEM_AGGR>>>(A_hat, out);
}

// round 12
// speedup vs baseline: 1.8551x; 1.0502x over previous
#include <cuda_runtime.h>
#include <cuda_fp16.h>
#include <cuda_bf16.h>
#include <cstdint>
#include <cstring>

// Problem dims (fixed by the reference)
#define NROWS   16384
#define INDIM   256
#define OUTDIM  128

// Stage-2 tiling
#define BM 128
#define BK 32
#define KT (NROWS / BK)      // 512

// smem (halfs): bufA[2] 128x40 fp16 (no B smem -- B fragments come straight
// from L2-resident g_h2 via LDG with register prefetch)
#define A_BUF_HALFS 5120     // 128 * 40
#define TILE_SMEM (2 * A_BUF_HALFS * 2)   // 20480 B
#define RED_SMEM  65536                   // split-K reduction
#define SMEM_AGGR (RED_SMEM > TILE_SMEM ? RED_SMEM : TILE_SMEM)

// Intermediate h in fp16, k-pair interleaved: word(kp, n) = g_h2w[kp*128 + n]
__device__ __half g_h2[(size_t)NROWS * OUTDIM];

// One dynamic-smem declaration for the whole TU.
extern __shared__ char dyn_smem[];

// ---------------------------------------------------------------------------
__device__ __forceinline__ uint32_t smem_u32(const void* p) {
    uint32_t a;
    asm("{ .reg .u64 t; cvta.to.shared.u64 t, %1; cvt.u32.u64 %0, t; }" : "=r"(a) : "l"(p));
    return a;
}
__device__ __forceinline__ uint32_t f2tf32_rn(float f) {
    uint32_t u;
    asm("cvt.rna.tf32.f32 %0, %1;" : "=r"(u) : "f"(f));
    return u;
}
__device__ __forceinline__ void mma_tf32(float c[4], const uint32_t a[4], const uint32_t b[2]) {
    asm volatile(
        "mma.sync.aligned.m16n8k8.row.col.f32.tf32.tf32.f32 "
        "{%0,%1,%2,%3}, {%4,%5,%6,%7}, {%8,%9}, {%0,%1,%2,%3};"
        : "+f"(c[0]), "+f"(c[1]), "+f"(c[2]), "+f"(c[3])
        : "r"(a[0]), "r"(a[1]), "r"(a[2]), "r"(a[3]), "r"(b[0]), "r"(b[1]));
}
__device__ __forceinline__ void mma_f16(float c[4], const uint32_t a[4], const uint32_t b[2]) {
    asm volatile(
        "mma.sync.aligned.m16n8k16.row.col.f32.f16.f16.f32 "
        "{%0,%1,%2,%3}, {%4,%5,%6,%7}, {%8,%9}, {%0,%1,%2,%3};"
        : "+f"(c[0]), "+f"(c[1]), "+f"(c[2]), "+f"(c[3])
        : "r"(a[0]), "r"(a[1]), "r"(a[2]), "r"(a[3]), "r"(b[0]), "r"(b[1]));
}
__device__ __forceinline__ void cp_async16(uint32_t saddr, const void* g) {
    asm volatile("cp.async.cg.shared.global [%0], [%1], 16;" :: "r"(saddr), "l"(g));
}
__device__ __forceinline__ void cp_commit() { asm volatile("cp.async.commit_group;"); }
__device__ __forceinline__ void ldsm_x4(uint32_t r[4], uint32_t saddr) {
    asm volatile("ldmatrix.sync.aligned.m8n8.x4.shared.b16 {%0,%1,%2,%3}, [%4];"
                 : "=r"(r[0]), "=r"(r[1]), "=r"(r[2]), "=r"(r[3]) : "r"(saddr));
}

// ============================================================================
// Stage 1: h = x @ W^T + b  (tf32, RN both sides) -> g_h2 fp16 interleaved
// ============================================================================
#define A_STRIDE 36
__global__ __launch_bounds__(256, 1)
void gemm_lin(const float* __restrict__ x, const float* __restrict__ W,
              const float* __restrict__ bias) {
    float* smem = (float*)dyn_smem;
    float* As0 = smem;
    float* As1 = As0 + BM * A_STRIDE;
    float* Ws0 = As1 + BM * A_STRIDE;
    float* Ws1 = Ws0 + OUTDIM * A_STRIDE;

    const int tid  = threadIdx.x;
    const int lane = tid & 31, wid = tid >> 5;
    const int warpM = wid >> 2, warpN = wid & 3;
    const int bm = blockIdx.x;

    uint32_t sA0 = smem_u32(As0), sA1 = smem_u32(As1);
    uint32_t sW0 = smem_u32(Ws0), sW1 = smem_u32(Ws1);

    float c[4][4][4];
#pragma unroll
    for (int i = 0; i < 4; i++)
#pragma unroll
        for (int j = 0; j < 4; j++)
#pragma unroll
            for (int k = 0; k < 4; k++) c[i][j][k] = 0.0f;

    auto load36 = [&](uint32_t sbase, const float* src, int row0, int k0, int ldK) {
#pragma unroll
        for (int t = 0; t < 4; t++) {
            int idx = tid + t * 256;
            int r = idx >> 3, cc = (idx & 7) << 2;
            cp_async16(sbase + (uint32_t)(r * A_STRIDE + cc) * 4u,
                       src + (size_t)(row0 + r) * ldK + k0 + cc);
        }
    };

    load36(sA0, x, bm * BM, 0, INDIM);
    load36(sW0, W, 0, 0, INDIM);
    cp_commit();

    const int KTL = INDIM / BK; // 8
    for (int kt = 0; kt < KTL; kt++) {
        asm volatile("cp.async.wait_group 0;" ::: "memory");
        __syncthreads();
        if (kt + 1 < KTL) {
            load36(((kt + 1) & 1) ? sA1 : sA0, x, bm * BM, (kt + 1) * BK, INDIM);
            load36(((kt + 1) & 1) ? sW1 : sW0, W, 0, (kt + 1) * BK, INDIM);
            cp_commit();
        }
        const float* As = (kt & 1) ? As1 : As0;
        const float* Ws = (kt & 1) ? Ws1 : Ws0;

#pragma unroll
        for (int kk = 0; kk < BK; kk += 8) {
            uint32_t af[4][4];
#pragma unroll
            for (int mi = 0; mi < 4; mi++) {
                int r  = warpM * 64 + mi * 16 + (lane >> 2);
                int cc = kk + (lane & 3);
                af[mi][0] = f2tf32_rn(As[r * A_STRIDE + cc]);
                af[mi][1] = f2tf32_rn(As[(r + 8) * A_STRIDE + cc]);
                af[mi][2] = f2tf32_rn(As[r * A_STRIDE + cc + 4]);
                af[mi][3] = f2tf32_rn(As[(r + 8) * A_STRIDE + cc + 4]);
            }
            uint32_t bf[4][2];
#pragma unroll
            for (int ni = 0; ni < 4; ni++) {
                int n = warpN * 32 + ni * 8 + (lane >> 2);
                int k = kk + (lane & 3);
                bf[ni][0] = f2tf32_rn(Ws[n * A_STRIDE + k]);
                bf[ni][1] = f2tf32_rn(Ws[n * A_STRIDE + k + 4]);
            }
#pragma unroll
            for (int mi = 0; mi < 4; mi++)
#pragma unroll
                for (int ni = 0; ni < 4; ni++) mma_tf32(c[mi][ni], af[mi], bf[ni]);
        }
        __syncthreads();
    }

    // Epilogue: bias add, fp16-RN, store into k-pair-interleaved g_h2.
#pragma unroll
    for (int ni = 0; ni < 4; ni++) {
        int cn = warpN * 32 + ni * 8 + ((lane & 3) << 1);
        float2 bb = *(const float2*)(bias + cn);
#pragma unroll
        for (int mi = 0; mi < 4; mi++) {
            int r0 = bm * BM + warpM * 64 + mi * 16 + (lane >> 2);
            int r1 = r0 + 8;
            size_t b0 = (size_t)(r0 >> 1) * 256 + (r0 & 1);
            size_t b1 = (size_t)(r1 >> 1) * 256 + (r1 & 1);
            g_h2[b0 + (size_t)cn * 2]       = __float2half_rn(c[mi][ni][0] + bb.x);
            g_h2[b0 + (size_t)(cn + 1) * 2] = __float2half_rn(c[mi][ni][1] + bb.y);
            g_h2[b1 + (size_t)cn * 2]       = __float2half_rn(c[mi][ni][2] + bb.x);
            g_h2[b1 + (size_t)(cn + 1) * 2] = __float2half_rn(c[mi][ni][3] + bb.y);
        }
    }
}

// ============================================================================
// Stage 2: out = A_hat @ h, fp16 HMMA m16n8k16.
// 512 threads, 16 warps = 2(M) x 4(N) x 2(K-split). Warp tile 64x32; one
// m16n8k16 k-step per warp per BK=32 tile.
// A fragments: ldmatrix.x4 from double-buffered smem (4 LDSM/warp-tile).
// B fragments: direct LDG.32 from L2-resident g_h2, 1-iter register prefetch.
// Only sync: one __syncthreads per iteration (A double buffer). No cp.async.
// ============================================================================
struct ARegs { float4 v[2]; };   // 8 floats: row tid>>2, k (tid&3)*8 .. +7

__device__ __forceinline__ void ldgA(ARegs& ra, const float* __restrict__ A,
                                     int bm, int kt, int tid) {
    const int row = tid >> 2, kc = (tid & 3) * 8;
    const float* p = A + (size_t)(bm * BM + row) * NROWS + kt * BK + kc;
    ra.v[0] = *(const float4*)p;
    ra.v[1] = *(const float4*)(p + 4);
}

__device__ __forceinline__ void stsA(__half* bufA, const ARegs& ra, int tid) {
    const int row = tid >> 2, kc = (tid & 3) * 8;
    const float* f = (const float*)&ra.v[0];
    __half2 h[4];
#pragma unroll
    for (int j = 0; j < 4; j++) h[j] = __floats2half2_rn(f[2 * j], f[2 * j + 1]);
    uint4 u;
    memcpy(&u, h, 16);
    *(uint4*)&bufA[row * 40 + kc] = u;
}

// B fragment LDG: bf[ni][r] for tile kt, straight from g_h2 (word view).
__device__ __forceinline__ void ldgB(uint32_t bf[4][2], int kt,
                                     int lane, int warpN, int warpK) {
    const uint32_t* gw = (const uint32_t*)g_h2;
    const int kp = kt * 16 + warpK * 8 + (lane & 3);
    const int n0 = warpN * 32 + (lane >> 2);
#pragma unroll
    for (int ni = 0; ni < 4; ni++) {
        const uint32_t* p = gw + (size_t)kp * 128 + n0 + ni * 8;
        bf[ni][0] = p[0];
        bf[ni][1] = p[4 * 128];
    }
}

__device__ __forceinline__ void computeTile(const __half* bufA, uint32_t saBase,
                                            const uint32_t bf[4][2],
                                            float c[4][4][4], int lane,
                                            int warpM, int warpN, int warpK) {
    // ldmatrix lane-address pattern (same for all mi, offset by mi*16 rows):
    // matrix j = lane>>3:  j0: rows r..r+7 k0..7 | j1: rows r+8..r+15 k0..7
    //                      j2: rows r..r+7 k8..15| j3: rows r+8..+15 k8..15
    const int rbase = warpM * 64 + ((lane >> 3) & 1) * 8 + (lane & 7);
    const int kloc  = warpK * 16 + (lane >> 4) * 8;
    uint32_t af[4][4];
#pragma unroll
    for (int mi = 0; mi < 4; mi++) {
        uint32_t sa = saBase + (uint32_t)(((rbase + mi * 16) * 40 + kloc) * 2);
        ldsm_x4(af[mi], sa);
    }
#pragma unroll
    for (int mi = 0; mi < 4; mi++)
#pragma unroll
        for (int ni = 0; ni < 4; ni++) mma_f16(c[mi][ni], af[mi], bf[ni]);
}

__global__ __launch_bounds__(512, 1)
void gemm_aggr(const float* __restrict__ A, float* __restrict__ out) {
    __half* sm = (__half*)dyn_smem;
    __half* bufA[2] = { sm, sm + A_BUF_HALFS };
    const uint32_t sa[2] = { smem_u32(bufA[0]), smem_u32(bufA[1]) };

    const int tid  = threadIdx.x;
    const int lane = tid & 31, wid = tid >> 5;     // wid 0..15
    const int warpK = wid >> 3;                    // 0,1
    const int warpM = (wid >> 2) & 1;              // 0,1
    const int warpN = wid & 3;                     // 0..3
    const int bm = blockIdx.x;

    float c[4][4][4];
#pragma unroll
    for (int i = 0; i < 4; i++)
#pragma unroll
        for (int j = 0; j < 4; j++)
#pragma unroll
            for (int k = 0; k < 4; k++) c[i][j][k] = 0.0f;

    // Prologue: A tile0 -> smem, A tile1 -> regs, B tile0 -> frag regs.
    ARegs ra;
    uint32_t bfr[2][4][2];
    {
        ARegs t0;
        ldgA(t0, A, bm, 0, tid);
        ldgB(bfr[0], 0, lane, warpN, warpK);
        stsA(bufA[0], t0, tid);
        ldgA(ra, A, bm, 1, tid);
        __syncthreads();
    }

    for (int kt = 0; kt < KT; kt++) {
        const int n1 = (kt + 1 < KT) ? kt + 1 : KT - 1;
        const int n2 = (kt + 2 < KT) ? kt + 2 : KT - 1;

        // Prefetches for future tiles (all latency covered by compute below).
        stsA(bufA[(kt + 1) & 1], ra, tid);          // A tile kt+1 -> other buffer
        ldgA(ra, A, bm, n2, tid);                   // A tile kt+2 -> regs
        ldgB(bfr[(kt + 1) & 1], n1, lane, warpN, warpK);  // B tile kt+1 -> regs

        // Compute tile kt.
        computeTile(bufA[kt & 1], sa[kt & 1], bfr[kt & 1], c,
                    lane, warpM, warpN, warpK);

        __syncthreads();   // A double-buffer epoch boundary
    }

    // ---- split-K reduction: warpK=1 -> smem, warpK=0 adds & stores ----
    float* red = (float*)dyn_smem;   // 8 warps * 2048 floats = 64 KB
    float4* cf4 = (float4*)&c[0][0][0];   // 16 float4 per thread
    __syncthreads();
    if (warpK == 1) {
        float4* dst = (float4*)(red + (wid - 8) * 2048);
#pragma unroll
        for (int i = 0; i < 16; i++) dst[i * 32 + lane] = cf4[i];
    }
    __syncthreads();
    if (warpK == 0) {
        const float4* src = (const float4*)(red + wid * 2048);
#pragma unroll
        for (int i = 0; i < 16; i++) {
            float4 v = src[i * 32 + lane];
            cf4[i].x += v.x; cf4[i].y += v.y; cf4[i].z += v.z; cf4[i].w += v.w;
        }
#pragma unroll
        for (int mi = 0; mi < 4; mi++)
#pragma unroll
            for (int ni = 0; ni < 4; ni++) {
                int r  = bm * BM + warpM * 64 + mi * 16 + (lane >> 2);
                int cn = warpN * 32 + ni * 8 + ((lane & 3) << 1);
                *(float2*)&out[(size_t)r * OUTDIM + cn] =
                    make_float2(c[mi][ni][0], c[mi][ni][1]);
                *(float2*)&out[(size_t)(r + 8) * OUTDIM + cn] =
                    make_float2(c[mi][ni][2], c[mi][ni][3]);
            }
    }
}

static const int SMEM_LIN = (2 * BM * A_STRIDE + 2 * OUTDIM * A_STRIDE) * 4;  // 73728

extern "C" void kernel_launch(void* const* d_in, const int* in_sizes, int n_in,
                              void* d_out, int out_size) {
    const float* x     = (const float*)d_in[0];
    const float* A_hat = (const float*)d_in[1];
    const float* W     = (const float*)d_in[2];
    const float* b     = (const float*)d_in[3];
    float* out = (float*)d_out;

    cudaFuncSetAttribute(gemm_lin,  cudaFuncAttributeMaxDynamicSharedMemorySize, SMEM_LIN);
    cudaFuncSetAttribute(gemm_aggr, cudaFuncAttributeMaxDynamicSharedMemorySize, SMEM_AGGR);

    gemm_lin<<<NROWS / BM, 256, SMEM_LIN>>>(x, W, b);
    gemm_aggr<<<NROWS / BM, 512, SMEM_AGGR>>>(A_hat, out);
}